// round 7
// baseline (speedup 1.0000x reference)
#include <cuda_runtime.h>
#include <math.h>

#define VOCAB 32000
#define Q4    8000     // float4 per row
#define KNN   32
#define NT    512

__device__ __forceinline__ float warp_max(float v) {
    #pragma unroll
    for (int o = 16; o > 0; o >>= 1) v = fmaxf(v, __shfl_xor_sync(0xFFFFFFFFu, v, o));
    return v;
}
__device__ __forceinline__ float warp_sum(float v) {
    #pragma unroll
    for (int o = 16; o > 0; o >>= 1) v += __shfl_xor_sync(0xFFFFFFFFu, v, o);
    return v;
}

__device__ __forceinline__ float4 ldlu4(const float4* p) {
    float4 r;
    asm volatile("ld.global.lu.v4.f32 {%0,%1,%2,%3}, [%4];"
                 : "=f"(r.x), "=f"(r.y), "=f"(r.z), "=f"(r.w) : "l"(p));
    return r;
}
__device__ __forceinline__ void stcs4(float4* p, float4 v) {
    asm volatile("st.global.cs.v4.f32 [%0], {%1,%2,%3,%4};"
                 :: "l"(p), "f"(v.x), "f"(v.y), "f"(v.z), "f"(v.w) : "memory");
}

__global__ __launch_bounds__(NT, 4)
void knn_model_kernel(const float* __restrict__ logits,
                      const int*   __restrict__ optor_vals,
                      const float* __restrict__ optor_dists,
                      const int*   __restrict__ const_vals,
                      const float* __restrict__ const_dists,
                      const int*   __restrict__ prev_words,
                      const float* __restrict__ optor_lamda,
                      const float* __restrict__ const_lamda,
                      const float* __restrict__ optor_temp,
                      const float* __restrict__ const_temp,
                      float*       __restrict__ out)
{
    __shared__ float red[16];
    __shared__ float scale_sh;

    const int r    = blockIdx.x;              // one row per CTA
    const int tid  = threadIdx.x;
    const int wid  = tid >> 5;
    const int lane = tid & 31;

    const float4* __restrict__ l4 = (const float4*)(logits + (size_t)r * VOCAB);
    float4* __restrict__ o4 = (float4*)(out + (size_t)r * VOCAB);
    float*  __restrict__ orow = out + (size_t)r * VOCAB;

    // ---- Pass A: read logits (DRAM), exp once, stage e in out[] (L2 dirty),
    //      accumulate block sum ----
    float s = 0.0f;
    #pragma unroll 4
    for (int i = tid; i < Q4; i += NT) {
        float4 x = l4[i];
        float4 e;
        e.x = __expf(fminf(x.x, 87.0f));
        e.y = __expf(fminf(x.y, 87.0f));
        e.z = __expf(fminf(x.z, 87.0f));
        e.w = __expf(fminf(x.w, 87.0f));
        o4[i] = e;                             // cached store: stays in L2
        s += (e.x + e.y) + (e.z + e.w);
    }
    s = warp_sum(s);
    if (lane == 0) red[wid] = s;
    __syncthreads();
    if (tid < 32) {
        float v = (lane < 16) ? red[lane] : 0.0f;
        v = warp_sum(v);
        if (lane == 0) {
            const int p = prev_words[r];
            const bool om = (p <= 88) | ((p >= 91) & (p <= 291));
            const bool cm = (p == 89) | (p == 90) | (p >= 292);
            const float ol = optor_lamda[0];
            const float cl = const_lamda[0];
            const float base = (om ? (1.0f - ol) : 0.0f) + (cm ? (1.0f - cl) : 0.0f);
            scale_sh = base / v;
        }
    }
    __syncthreads();
    const float scale = scale_sh;

    // ---- Pass C: re-read e from out[] (L2 hit, last-use), scale, stream out ----
    #pragma unroll 4
    for (int i = tid; i < Q4; i += NT) {
        float4 e = ldlu4(&o4[i]);
        float4 y;
        y.x = e.x * scale;
        y.y = e.y * scale;
        y.z = e.z * scale;
        y.w = e.w * scale;
        stcs4(&o4[i], y);
    }
    __syncthreads();   // all base stores issued before scatter atomics

    // ---- Scatter: warp 0 = optor, warp 1 = const ----
    if (wid == 0) {
        const int p = prev_words[r];
        const bool om = (p <= 88) | ((p >= 91) & (p <= 291));
        const float t = optor_temp[0];
        const float d = optor_dists[(size_t)r * KNN + lane];
        const float x = -d / t;
        const float mm = warp_max(x);
        const float e  = __expf(x - mm);
        const float ss = warp_sum(e);
        if (om) atomicAdd(&orow[optor_vals[(size_t)r * KNN + lane]],
                          optor_lamda[0] * e / ss);
    } else if (wid == 1) {
        const int p = prev_words[r];
        const bool cm = (p == 89) | (p == 90) | (p >= 292);
        const float t = const_temp[0];
        const float d = const_dists[(size_t)r * KNN + lane];
        const float x = -d / t;
        const float mm = warp_max(x);
        const float e  = __expf(x - mm);
        const float ss = warp_sum(e);
        if (cm) atomicAdd(&orow[const_vals[(size_t)r * KNN + lane]],
                          const_lamda[0] * e / ss);
    }
}

extern "C" void kernel_launch(void* const* d_in, const int* in_sizes, int n_in,
                              void* d_out, int out_size)
{
    const float* logits      = (const float*)d_in[0];
    const int*   optor_vals  = (const int*)  d_in[1];
    const float* optor_dists = (const float*)d_in[2];
    const int*   const_vals  = (const int*)  d_in[3];
    const float* const_dists = (const float*)d_in[4];
    const int*   prev_words  = (const int*)  d_in[5];
    const float* optor_lamda = (const float*)d_in[6];
    const float* const_lamda = (const float*)d_in[7];
    const float* optor_temp  = (const float*)d_in[8];
    const float* const_temp  = (const float*)d_in[9];
    float* out = (float*)d_out;

    const int rows = in_sizes[5];                 // B*S = 1024

    knn_model_kernel<<<rows, NT>>>(
        logits, optor_vals, optor_dists, const_vals, const_dists,
        prev_words, optor_lamda, const_lamda, optor_temp, const_temp, out);
}

// round 8
// speedup vs baseline: 1.2885x; 1.2885x over previous
#include <cuda_runtime.h>
#include <math.h>

#define VOCAB 32000
#define Q4    8000     // float4 per row
#define KNN   32
#define NT    256
#define LOG2E 1.4426950408889634f

__device__ __forceinline__ float warp_max(float v) {
    #pragma unroll
    for (int o = 16; o > 0; o >>= 1) v = fmaxf(v, __shfl_xor_sync(0xFFFFFFFFu, v, o));
    return v;
}
__device__ __forceinline__ float warp_sum(float v) {
    #pragma unroll
    for (int o = 16; o > 0; o >>= 1) v += __shfl_xor_sync(0xFFFFFFFFu, v, o);
    return v;
}

__device__ __forceinline__ float4 ldlu4(const float4* p) {
    float4 r;
    asm volatile("ld.global.lu.v4.f32 {%0,%1,%2,%3}, [%4];"
                 : "=f"(r.x), "=f"(r.y), "=f"(r.z), "=f"(r.w) : "l"(p));
    return r;
}
__device__ __forceinline__ void stcs4(float4* p, float4 v) {
    asm volatile("st.global.cs.v4.f32 [%0], {%1,%2,%3,%4};"
                 :: "l"(p), "f"(v.x), "f"(v.y), "f"(v.z), "f"(v.w) : "memory");
}

__global__ __launch_bounds__(NT, 8)
void knn_model_kernel(const float* __restrict__ logits,
                      const int*   __restrict__ optor_vals,
                      const float* __restrict__ optor_dists,
                      const int*   __restrict__ const_vals,
                      const float* __restrict__ const_dists,
                      const int*   __restrict__ prev_words,
                      const float* __restrict__ optor_lamda,
                      const float* __restrict__ const_lamda,
                      const float* __restrict__ optor_temp,
                      const float* __restrict__ const_temp,
                      float*       __restrict__ out)
{
    __shared__ float red[8];
    __shared__ float lscale_sh;

    const int r    = blockIdx.x;              // one row per CTA
    const int tid  = threadIdx.x;
    const int wid  = tid >> 5;
    const int lane = tid & 31;

    const float4* __restrict__ l4 = (const float4*)(logits + (size_t)r * VOCAB);
    float4* __restrict__ o4 = (float4*)(out + (size_t)r * VOCAB);
    float*  __restrict__ orow = out + (size_t)r * VOCAB;

    // ---- Pass A: read logits (DRAM -> L2), exp2(x*log2e), block sum ----
    float s = 0.0f;
    #pragma unroll 4
    for (int i = tid; i < Q4; i += NT) {
        float4 x = l4[i];
        s += exp2f(x.x * LOG2E) + exp2f(x.y * LOG2E)
           + exp2f(x.z * LOG2E) + exp2f(x.w * LOG2E);
    }
    s = warp_sum(s);
    if (lane == 0) red[wid] = s;
    __syncthreads();
    if (tid < 32) {
        float v = (lane < 8) ? red[lane] : 0.0f;
        v = warp_sum(v);
        if (lane == 0) {
            const int p = prev_words[r];
            const bool om = (p <= 88) | ((p >= 91) & (p <= 291));
            const bool cm = (p == 89) | (p == 90) | (p >= 292);
            const float ol = optor_lamda[0];
            const float cl = const_lamda[0];
            const float base = (om ? (1.0f - ol) : 0.0f) + (cm ? (1.0f - cl) : 0.0f);
            lscale_sh = log2f(base / v);      // scale > 0 always (masks exhaustive)
        }
    }
    __syncthreads();
    const float lscale = lscale_sh;

    // ---- Pass C: re-read x (L2 hit, last-use), y = exp2(x*log2e + lscale) ----
    #pragma unroll 4
    for (int i = tid; i < Q4; i += NT) {
        float4 x = ldlu4(&l4[i]);
        float4 y;
        y.x = exp2f(fmaf(x.x, LOG2E, lscale));
        y.y = exp2f(fmaf(x.y, LOG2E, lscale));
        y.z = exp2f(fmaf(x.z, LOG2E, lscale));
        y.w = exp2f(fmaf(x.w, LOG2E, lscale));
        stcs4(&o4[i], y);
    }
    __syncthreads();   // all base stores issued before scatter atomics

    // ---- Scatter: warp 0 = optor, warp 1 = const ----
    if (wid == 0) {
        const int p = prev_words[r];
        const bool om = (p <= 88) | ((p >= 91) & (p <= 291));
        const float t = optor_temp[0];
        const float d = optor_dists[(size_t)r * KNN + lane];
        const float x = -d / t;
        const float mm = warp_max(x);
        const float e  = __expf(x - mm);
        const float ss = warp_sum(e);
        if (om) atomicAdd(&orow[optor_vals[(size_t)r * KNN + lane]],
                          optor_lamda[0] * e / ss);
    } else if (wid == 1) {
        const int p = prev_words[r];
        const bool cm = (p == 89) | (p == 90) | (p >= 292);
        const float t = const_temp[0];
        const float d = const_dists[(size_t)r * KNN + lane];
        const float x = -d / t;
        const float mm = warp_max(x);
        const float e  = __expf(x - mm);
        const float ss = warp_sum(e);
        if (cm) atomicAdd(&orow[const_vals[(size_t)r * KNN + lane]],
                          const_lamda[0] * e / ss);
    }
}

extern "C" void kernel_launch(void* const* d_in, const int* in_sizes, int n_in,
                              void* d_out, int out_size)
{
    const float* logits      = (const float*)d_in[0];
    const int*   optor_vals  = (const int*)  d_in[1];
    const float* optor_dists = (const float*)d_in[2];
    const int*   const_vals  = (const int*)  d_in[3];
    const float* const_dists = (const float*)d_in[4];
    const int*   prev_words  = (const int*)  d_in[5];
    const float* optor_lamda = (const float*)d_in[6];
    const float* const_lamda = (const float*)d_in[7];
    const float* optor_temp  = (const float*)d_in[8];
    const float* const_temp  = (const float*)d_in[9];
    float* out = (float*)d_out;

    const int rows = in_sizes[5];                 // B*S = 1024

    knn_model_kernel<<<rows, NT>>>(
        logits, optor_vals, optor_dists, const_vals, const_dists,
        prev_words, optor_lamda, const_lamda, optor_temp, const_temp, out);
}

// round 9
// speedup vs baseline: 1.4896x; 1.1561x over previous
#include <cuda_runtime.h>
#include <math.h>

#define VOCAB 32000
#define Q4    8000     // float4 per row
#define KNN   32
#define NT    512
#define LOG2E 1.4426950408889634f

__device__ __forceinline__ float warp_max(float v) {
    #pragma unroll
    for (int o = 16; o > 0; o >>= 1) v = fmaxf(v, __shfl_xor_sync(0xFFFFFFFFu, v, o));
    return v;
}
__device__ __forceinline__ float warp_sum(float v) {
    #pragma unroll
    for (int o = 16; o > 0; o >>= 1) v += __shfl_xor_sync(0xFFFFFFFFu, v, o);
    return v;
}

__device__ __forceinline__ float4 ldlu4(const float4* p) {
    float4 r;
    asm volatile("ld.global.lu.v4.f32 {%0,%1,%2,%3}, [%4];"
                 : "=f"(r.x), "=f"(r.y), "=f"(r.z), "=f"(r.w) : "l"(p));
    return r;
}
__device__ __forceinline__ void stcs4(float4* p, float4 v) {
    asm volatile("st.global.cs.v4.f32 [%0], {%1,%2,%3,%4};"
                 :: "l"(p), "f"(v.x), "f"(v.y), "f"(v.z), "f"(v.w) : "memory");
}

__global__ __launch_bounds__(NT, 4)
void knn_model_kernel(const float* __restrict__ logits,
                      const int*   __restrict__ optor_vals,
                      const float* __restrict__ optor_dists,
                      const int*   __restrict__ const_vals,
                      const float* __restrict__ const_dists,
                      const int*   __restrict__ prev_words,
                      const float* __restrict__ optor_lamda,
                      const float* __restrict__ const_lamda,
                      const float* __restrict__ optor_temp,
                      const float* __restrict__ const_temp,
                      float*       __restrict__ out)
{
    __shared__ float red[16];
    __shared__ float lscale_sh;

    const int r    = blockIdx.x;              // one row per CTA
    const int tid  = threadIdx.x;
    const int wid  = tid >> 5;
    const int lane = tid & 31;

    const float4* __restrict__ l4 = (const float4*)(logits + (size_t)r * VOCAB);
    float4* __restrict__ o4 = (float4*)(out + (size_t)r * VOCAB);
    float*  __restrict__ orow = out + (size_t)r * VOCAB;

    // ---- Pass A: read logits (DRAM -> L2), exp2(x*log2e), block sum ----
    float s = 0.0f;
    #pragma unroll 4
    for (int i = tid; i < Q4; i += NT) {
        float4 x = l4[i];
        s += exp2f(x.x * LOG2E) + exp2f(x.y * LOG2E)
           + exp2f(x.z * LOG2E) + exp2f(x.w * LOG2E);
    }
    s = warp_sum(s);
    if (lane == 0) red[wid] = s;
    __syncthreads();
    if (tid < 32) {
        float v = (lane < 16) ? red[lane] : 0.0f;
        v = warp_sum(v);
        if (lane == 0) {
            const int p = prev_words[r];
            const bool om = (p <= 88) | ((p >= 91) & (p <= 291));
            const bool cm = (p == 89) | (p == 90) | (p >= 292);
            const float ol = optor_lamda[0];
            const float cl = const_lamda[0];
            const float base = (om ? (1.0f - ol) : 0.0f) + (cm ? (1.0f - cl) : 0.0f);
            lscale_sh = log2f(base / v);      // scale > 0 always (masks exhaustive)
        }
    }
    __syncthreads();
    const float lscale = lscale_sh;

    // ---- Pass C: re-read x (L2 hit, last-use), y = exp2(x*log2e + lscale) ----
    #pragma unroll 4
    for (int i = tid; i < Q4; i += NT) {
        float4 x = ldlu4(&l4[i]);
        float4 y;
        y.x = exp2f(fmaf(x.x, LOG2E, lscale));
        y.y = exp2f(fmaf(x.y, LOG2E, lscale));
        y.z = exp2f(fmaf(x.z, LOG2E, lscale));
        y.w = exp2f(fmaf(x.w, LOG2E, lscale));
        stcs4(&o4[i], y);
    }
    __syncthreads();   // all base stores issued before scatter atomics

    // ---- Scatter: warp 0 = optor, warp 1 = const ----
    if (wid == 0) {
        const int p = prev_words[r];
        const bool om = (p <= 88) | ((p >= 91) & (p <= 291));
        const float t = optor_temp[0];
        const float d = optor_dists[(size_t)r * KNN + lane];
        const float x = -d / t;
        const float mm = warp_max(x);
        const float e  = __expf(x - mm);
        const float ss = warp_sum(e);
        if (om) atomicAdd(&orow[optor_vals[(size_t)r * KNN + lane]],
                          optor_lamda[0] * e / ss);
    } else if (wid == 1) {
        const int p = prev_words[r];
        const bool cm = (p == 89) | (p == 90) | (p >= 292);
        const float t = const_temp[0];
        const float d = const_dists[(size_t)r * KNN + lane];
        const float x = -d / t;
        const float mm = warp_max(x);
        const float e  = __expf(x - mm);
        const float ss = warp_sum(e);
        if (cm) atomicAdd(&orow[const_vals[(size_t)r * KNN + lane]],
                          const_lamda[0] * e / ss);
    }
}

extern "C" void kernel_launch(void* const* d_in, const int* in_sizes, int n_in,
                              void* d_out, int out_size)
{
    const float* logits      = (const float*)d_in[0];
    const int*   optor_vals  = (const int*)  d_in[1];
    const float* optor_dists = (const float*)d_in[2];
    const int*   const_vals  = (const int*)  d_in[3];
    const float* const_dists = (const float*)d_in[4];
    const int*   prev_words  = (const int*)  d_in[5];
    const float* optor_lamda = (const float*)d_in[6];
    const float* const_lamda = (const float*)d_in[7];
    const float* optor_temp  = (const float*)d_in[8];
    const float* const_temp  = (const float*)d_in[9];
    float* out = (float*)d_out;

    const int rows = in_sizes[5];                 // B*S = 1024

    knn_model_kernel<<<rows, NT>>>(
        logits, optor_vals, optor_dists, const_vals, const_dists,
        prev_words, optor_lamda, const_lamda, optor_temp, const_temp, out);
}